// round 8
// baseline (speedup 1.0000x reference)
#include <cuda_runtime.h>
#include <cuda_bf16.h>
#include <math.h>

#define BZ 32
#define SZ 128
#define HZ 768
#define MH_ 6
#define KK 4

__constant__ float c_inv[8] = {1.f, 1.f/2.f, 1.f/3.f, 1.f/4.f, 1.f/5.f, 1.f/6.f, 1.f/7.f, 1.f/8.f};

__device__ unsigned long long g_cand[BZ * 2 * 4 * 4];  // [b][type][quarter][4]
__device__ unsigned int g_tick[BZ];                    // zero-init; elected resets

#define CE(x, y) { unsigned long long _a = (x), _b = (y); (x) = _a > _b ? _a : _b; (y) = _a > _b ? _b : _a; }

// Butterfly merge of per-lane sorted-4 desc lists -> warp-wide top-4 in every lane.
#define WARP_MERGE4(k0, k1, k2, k3)                                            \
    _Pragma("unroll")                                                          \
    for (int off = 16; off; off >>= 1) {                                       \
        unsigned long long o0 = __shfl_xor_sync(0xFFFFFFFFu, k0, off);         \
        unsigned long long o1 = __shfl_xor_sync(0xFFFFFFFFu, k1, off);         \
        unsigned long long o2 = __shfl_xor_sync(0xFFFFFFFFu, k2, off);         \
        unsigned long long o3 = __shfl_xor_sync(0xFFFFFFFFu, k3, off);         \
        unsigned long long c0 = k0 > o3 ? k0 : o3;                             \
        unsigned long long c1 = k1 > o2 ? k1 : o2;                             \
        unsigned long long c2 = k2 > o1 ? k2 : o1;                             \
        unsigned long long c3 = k3 > o0 ? k3 : o0;                             \
        CE(c0, c2); CE(c1, c3); CE(c0, c1); CE(c2, c3);                        \
        k0 = c0; k1 = c1; k2 = c2; k3 = c3;                                    \
    }

// out layout (floats): implicit[0,512) explicit[512,2560) hs[2560,35328) ts[35328,68096)

__global__ __launch_bounds__(256, 1) void k_all(
    const float* __restrict__ emb,
    const int* __restrict__ mask,
    const float* __restrict__ wh,
    const float* __restrict__ bh_,
    const float* __restrict__ wt,
    const float* __restrict__ bt_,
    const float* __restrict__ wi,
    const float* __restrict__ bi,
    const float* __restrict__ we,
    const float* __restrict__ be,
    float* __restrict__ out)
{
    __shared__ __align__(16) float swh[HZ];   // 3 KB
    __shared__ __align__(16) float swt[HZ];   // 3 KB
    __shared__ float sdot[2][40];             // [0]=target(wt), [1]=holder(wh)
    __shared__ unsigned long long cand[2][32];
    __shared__ float topv[2][KK];
    __shared__ int   topi[2][KK];
    __shared__ float partial[8][8];
    __shared__ float sbias[8];                // 0-3: bi, 4-7: be
    __shared__ float s_bh, s_bt;
    __shared__ int s_flag, s_len;

    const int b = blockIdx.x, q = blockIdx.y;
    const int tid = threadIdx.x;
    const int warp = tid >> 5, lane = tid & 31;
    const float* eb = emb + (size_t)b * SZ * HZ;

    // ---- stage wh/wt to smem; scalars; mask length (warp 1) ----
    {
        float4* swh4 = (float4*)swh;
        float4* swt4 = (float4*)swt;
        for (int j = tid; j < 384; j += 256) {
            if (j < 192) swh4[j] = ((const float4*)wh)[j];
            else         swt4[j - 192] = ((const float4*)wt)[j - 192];
        }
        if (tid == 0) s_flag = 0;
        if (tid < 4)            sbias[tid] = bi[tid];
        else if (tid < 8)       sbias[tid] = be[tid - 4];
        if (tid == 8)  s_bh = bh_[0];
        if (tid == 9)  s_bt = bt_[0];
        if (warp == 1) {
            int4 mv = ((const int4*)(mask + b * SZ))[lane];
            int v = mv.x + mv.y + mv.z + mv.w;
#pragma unroll
            for (int off = 16; off; off >>= 1) v += __shfl_xor_sync(0xFFFFFFFFu, v, off);
            if (lane == 0) s_len = v;
        }
    }
    __syncthreads();

    // ---- phase A: row dots for rows q*32 .. q*32+39 (5 rows/warp) ----
    {
        const int r0 = q * 32 + warp * 5;
        float4 v[5][6];
#pragma unroll
        for (int r = 0; r < 5; r++) {
            int row = r0 + r;
            if (row < SZ) {
                const float4* rp = (const float4*)(eb + (size_t)row * HZ);
#pragma unroll
                for (int i = 0; i < 6; i++) v[r][i] = rp[lane + 32 * i];
            } else {
#pragma unroll
                for (int i = 0; i < 6; i++) v[r][i] = make_float4(0.f,0.f,0.f,0.f);
            }
        }
        float ah[5], at[5];
        const float4* swh4 = (const float4*)swh;
        const float4* swt4 = (const float4*)swt;
#pragma unroll
        for (int r = 0; r < 5; r++) { ah[r] = 0.f; at[r] = 0.f; }
#pragma unroll
        for (int i = 0; i < 6; i++) {
            float4 wv = swh4[lane + 32 * i];
            float4 tv = swt4[lane + 32 * i];
#pragma unroll
            for (int r = 0; r < 5; r++) {
                ah[r] += v[r][i].x * wv.x + v[r][i].y * wv.y
                       + v[r][i].z * wv.z + v[r][i].w * wv.w;
                at[r] += v[r][i].x * tv.x + v[r][i].y * tv.y
                       + v[r][i].z * tv.z + v[r][i].w * tv.w;
            }
        }
#pragma unroll
        for (int off = 16; off; off >>= 1) {
#pragma unroll
            for (int r = 0; r < 5; r++) {
                ah[r] += __shfl_xor_sync(0xFFFFFFFFu, ah[r], off);
                at[r] += __shfl_xor_sync(0xFFFFFFFFu, at[r], off);
            }
        }
        if (lane == 0) {
#pragma unroll
            for (int r = 0; r < 5; r++) {
                sdot[0][warp * 5 + r] = at[r];
                sdot[1][warp * 5 + r] = ah[r];
            }
        }
    }
    __syncthreads();

    // ---- scores (warp = width m, lane = local start), keys, warp top-4 ----
    {
        const int m = warp;                 // width index 0..7
        const int sl = lane;                // local start 0..31
        const int sg = q * 32 + sl;
        const int gidx = m * SZ + sg;
        float st = 0.f, sh = 0.f;
        for (int r = 0; r <= m; r++) {      // uniform across warp
            st += sdot[0][sl + r];
            sh += sdot[1][sl + r];
        }
        const float invw = c_inv[m];
        const int len = s_len;
        bool tv = (sg + m) < len;
        bool hv = tv && (m < MH_);
        float vt = tv ? 1.f / (1.f + __expf(-(st * invw + s_bt))) : -1.f;
        float vh = hv ? 1.f / (1.f + __expf(-(sh * invw + s_bh))) : -1.f;
        out[35328 + (size_t)b * 1024 + gidx] = vt;
        out[2560  + (size_t)b * 1024 + gidx] = vh;

        unsigned ut = __float_as_uint(vt);
        unsigned uh = __float_as_uint(vh);
        ut = (ut & 0x80000000u) ? ~ut : (ut | 0x80000000u);
        uh = (uh & 0x80000000u) ? ~uh : (uh | 0x80000000u);
        unsigned long long t0 = ((unsigned long long)ut << 32) | (unsigned)(0xFFFFFFFFu - gidx);
        unsigned long long h0 = ((unsigned long long)uh << 32) | (unsigned)(0xFFFFFFFFu - gidx);
        unsigned long long t1 = 0ull, t2 = 0ull, t3 = 0ull;
        unsigned long long h1 = 0ull, h2 = 0ull, h3 = 0ull;
        // interleaved butterfly merges (t and h chains independent)
#pragma unroll
        for (int off = 16; off; off >>= 1) {
            unsigned long long ot0 = __shfl_xor_sync(0xFFFFFFFFu, t0, off);
            unsigned long long oh0 = __shfl_xor_sync(0xFFFFFFFFu, h0, off);
            unsigned long long ot1 = __shfl_xor_sync(0xFFFFFFFFu, t1, off);
            unsigned long long oh1 = __shfl_xor_sync(0xFFFFFFFFu, h1, off);
            unsigned long long ot2 = __shfl_xor_sync(0xFFFFFFFFu, t2, off);
            unsigned long long oh2 = __shfl_xor_sync(0xFFFFFFFFu, h2, off);
            unsigned long long ot3 = __shfl_xor_sync(0xFFFFFFFFu, t3, off);
            unsigned long long oh3 = __shfl_xor_sync(0xFFFFFFFFu, h3, off);
            unsigned long long a0 = t0 > ot3 ? t0 : ot3;
            unsigned long long a1 = t1 > ot2 ? t1 : ot2;
            unsigned long long a2 = t2 > ot1 ? t2 : ot1;
            unsigned long long a3 = t3 > ot0 ? t3 : ot0;
            unsigned long long b0 = h0 > oh3 ? h0 : oh3;
            unsigned long long b1 = h1 > oh2 ? h1 : oh2;
            unsigned long long b2 = h2 > oh1 ? h2 : oh1;
            unsigned long long b3 = h3 > oh0 ? h3 : oh0;
            CE(a0, a2); CE(b0, b2);
            CE(a1, a3); CE(b1, b3);
            CE(a0, a1); CE(b0, b1);
            CE(a2, a3); CE(b2, b3);
            t0 = a0; t1 = a1; t2 = a2; t3 = a3;
            h0 = b0; h1 = b1; h2 = b2; h3 = b3;
        }
        if (lane == 0) {
            cand[0][warp * 4 + 0] = t0; cand[0][warp * 4 + 1] = t1;
            cand[0][warp * 4 + 2] = t2; cand[0][warp * 4 + 3] = t3;
            cand[1][warp * 4 + 0] = h0; cand[1][warp * 4 + 1] = h1;
            cand[1][warp * 4 + 2] = h2; cand[1][warp * 4 + 3] = h3;
        }
    }
    __syncthreads();

    // ---- block merge 32 -> 4 (warp0 targets, warp1 holders) -> g_cand ----
    if (warp < 2) {
        unsigned long long k0 = cand[warp][lane], k1 = 0ull, k2 = 0ull, k3 = 0ull;
        WARP_MERGE4(k0, k1, k2, k3);
        if (lane == 0) {
            unsigned long long* dst = &g_cand[((b * 2 + warp) * 4 + q) * 4];
            dst[0] = k0; dst[1] = k1; dst[2] = k2; dst[3] = k3;
        }
    }
    __syncthreads();

    // ---- election: 4th arriving block of this batch runs the tail ----
    __threadfence();
    __syncthreads();
    if (tid == 0) {
        unsigned old = atomicAdd(&g_tick[b], 1u);
        if (old == 3u) s_flag = 1;
    }
    __syncthreads();
    if (!s_flag) return;
    if (tid == 0) g_tick[b] = 0;
    __threadfence();

    // ================= Tail (one block per batch) =========================
    // merge 16 candidates per type
    if (warp < 2) {
        unsigned long long k0 = (lane < 16) ? g_cand[(b * 2 + warp) * 16 + lane] : 0ull;
        unsigned long long k1 = 0ull, k2 = 0ull, k3 = 0ull;
        WARP_MERGE4(k0, k1, k2, k3);
        if (lane == 0) {
            unsigned long long ks[4] = {k0, k1, k2, k3};
#pragma unroll
            for (int k = 0; k < KK; k++) {
                unsigned hi = (unsigned)(ks[k] >> 32);
                unsigned lo = (unsigned)ks[k];
                float v = (hi & 0x80000000u) ? __uint_as_float(hi ^ 0x80000000u)
                                             : __uint_as_float(~hi);
                topv[warp][k] = v;
                topi[warp][k] = (int)(0xFFFFFFFFu - lo);
            }
        }
    }
    __syncthreads();

    // rep dots: 1 warp per selected span (warps 0-3 target, 4-7 holder)
    {
        const int type = warp >> 2;
        const int k = warp & 3;
        const int idx = topi[type][k];
        const bool valid = topv[type][k] > 0.f;
        const int m = idx >> 7, s = idx & 127;
        const float invw = c_inv[m];
        const float4* wi4 = (const float4*)wi;
        const float4* we4 = (const float4*)we;

        float acc[8] = {0.f,0.f,0.f,0.f,0.f,0.f,0.f,0.f};
        if (valid) {
            float4 sum[6];
#pragma unroll
            for (int i = 0; i < 6; i++) sum[i] = make_float4(0.f,0.f,0.f,0.f);
#pragma unroll
            for (int r = 0; r < 8; r++) {
                if (r <= m) {
                    const float4* rp = (const float4*)(eb + (size_t)(s + r) * HZ);
#pragma unroll
                    for (int i = 0; i < 6; i++) {
                        float4 a = rp[lane + 32 * i];
                        sum[i].x += a.x; sum[i].y += a.y;
                        sum[i].z += a.z; sum[i].w += a.w;
                    }
                }
            }
#pragma unroll
            for (int i = 0; i < 6; i++) {
                int h4 = lane + 32 * i;
                float sv[4] = {sum[i].x * invw, sum[i].y * invw,
                               sum[i].z * invw, sum[i].w * invw};
#pragma unroll
                for (int j = 0; j < 4; j++) {
                    int f = 4 * h4 + j;
                    if (type == 0) {
                        float4 wv = wi4[f];
                        acc[0] += sv[j] * wv.x; acc[1] += sv[j] * wv.y;
                        acc[2] += sv[j] * wv.z; acc[3] += sv[j] * wv.w;
                        float4 ev = we4[HZ + f];
                        acc[4] += sv[j] * ev.x; acc[5] += sv[j] * ev.y;
                        acc[6] += sv[j] * ev.z; acc[7] += sv[j] * ev.w;
                    } else {
                        float4 ev = we4[f];
                        acc[0] += sv[j] * ev.x; acc[1] += sv[j] * ev.y;
                        acc[2] += sv[j] * ev.z; acc[3] += sv[j] * ev.w;
                    }
                }
            }
        }
#pragma unroll
        for (int off = 16; off; off >>= 1)
#pragma unroll
            for (int j = 0; j < 8; j++)
                acc[j] += __shfl_xor_sync(0xFFFFFFFFu, acc[j], off);
        if (lane == 0) {
#pragma unroll
            for (int j = 0; j < 8; j++) partial[warp][j] = acc[j];
        }
    }
    __syncthreads();

    // logits
    if (tid < 64) {
        int k = tid >> 4, i = (tid >> 2) & 3, j = tid & 3;
        bool pv = (topv[1][k] > 0.f) && (topv[0][i] > 0.f);
        float val = sbias[4 + j];
        if (pv) val += partial[4 + k][j] + partial[i][4 + j];
        out[512 + (size_t)b * 64 + tid] = val;
    } else if (tid < 80) {
        int t2 = tid - 64;
        int i = t2 >> 2, j = t2 & 3;
        float val = sbias[j];
        if (topv[0][i] > 0.f) val += partial[i][j];
        out[(size_t)b * 16 + t2] = val;
    }
}

extern "C" void kernel_launch(void* const* d_in, const int* in_sizes, int n_in,
                              void* d_out, int out_size)
{
    const float* emb = (const float*)d_in[0];
    const int*   msk = (const int*)d_in[1];
    const float* wh  = (const float*)d_in[2];
    const float* bh  = (const float*)d_in[3];
    const float* wt  = (const float*)d_in[4];
    const float* bt  = (const float*)d_in[5];
    const float* wi  = (const float*)d_in[6];
    const float* bi  = (const float*)d_in[7];
    const float* we  = (const float*)d_in[8];
    const float* be  = (const float*)d_in[9];
    float* out = (float*)d_out;

    dim3 g(BZ, 4, 1);
    k_all<<<g, 256>>>(emb, msk, wh, bh, wt, bt, wi, bi, we, be, out);
}

// round 9
// speedup vs baseline: 1.0022x; 1.0022x over previous
#include <cuda_runtime.h>
#include <cuda_bf16.h>
#include <math.h>

#define BZ 32
#define SZ 128
#define HZ 768
#define MH_ 6
#define KK 4

__constant__ float c_inv[8] = {1.f, 1.f/2.f, 1.f/3.f, 1.f/4.f, 1.f/5.f, 1.f/6.f, 1.f/7.f, 1.f/8.f};

__device__ unsigned long long g_cand[BZ * 2 * 4 * 4];  // [b][type][quarter][4]
__device__ unsigned int g_tick[BZ];                    // zero-init; elected resets

#define CE(x, y) { unsigned long long _a = (x), _b = (y); (x) = _a > _b ? _a : _b; (y) = _a > _b ? _b : _a; }

// Butterfly merge of per-lane sorted-4 desc lists -> warp-wide top-4 in every lane.
#define WARP_MERGE4(k0, k1, k2, k3)                                            \
    _Pragma("unroll")                                                          \
    for (int off = 16; off; off >>= 1) {                                       \
        unsigned long long o0 = __shfl_xor_sync(0xFFFFFFFFu, k0, off);         \
        unsigned long long o1 = __shfl_xor_sync(0xFFFFFFFFu, k1, off);         \
        unsigned long long o2 = __shfl_xor_sync(0xFFFFFFFFu, k2, off);         \
        unsigned long long o3 = __shfl_xor_sync(0xFFFFFFFFu, k3, off);         \
        unsigned long long c0 = k0 > o3 ? k0 : o3;                             \
        unsigned long long c1 = k1 > o2 ? k1 : o2;                             \
        unsigned long long c2 = k2 > o1 ? k2 : o1;                             \
        unsigned long long c3 = k3 > o0 ? k3 : o0;                             \
        CE(c0, c2); CE(c1, c3); CE(c0, c1); CE(c2, c3);                        \
        k0 = c0; k1 = c1; k2 = c2; k3 = c3;                                    \
    }

// out layout (floats): implicit[0,512) explicit[512,2560) hs[2560,35328) ts[35328,68096)

__global__ __launch_bounds__(512, 1) void k_all(
    const float* __restrict__ emb,
    const int* __restrict__ mask,
    const float* __restrict__ wh,
    const float* __restrict__ bh_,
    const float* __restrict__ wt,
    const float* __restrict__ bt_,
    const float* __restrict__ wi,
    const float* __restrict__ bi,
    const float* __restrict__ we,
    const float* __restrict__ be,
    float* __restrict__ out)
{
    __shared__ __align__(16) float swh[HZ];   // 3 KB
    __shared__ __align__(16) float swt[HZ];   // 3 KB
    __shared__ float sdot[2][40];             // [0]=target(wt), [1]=holder(wh)
    __shared__ unsigned long long cand[2][32];
    __shared__ float topv[2][KK];
    __shared__ int   topi[2][KK];
    __shared__ float partial[16][8];
    __shared__ float sbias[8];                // 0-3: bi, 4-7: be
    __shared__ float s_bh, s_bt;
    __shared__ int s_flag, s_len;

    const int b = blockIdx.x, q = blockIdx.y;
    const int tid = threadIdx.x;
    const int warp = tid >> 5, lane = tid & 31;
    const float* eb = emb + (size_t)b * SZ * HZ;

    // ---- stage wh/wt to smem; scalars; mask length (warp 1) ----
    {
        float4* swh4 = (float4*)swh;
        float4* swt4 = (float4*)swt;
        if (tid < 384) {
            if (tid < 192) swh4[tid] = ((const float4*)wh)[tid];
            else           swt4[tid - 192] = ((const float4*)wt)[tid - 192];
        }
        if (tid == 0) s_flag = 0;
        if (tid < 4)            sbias[tid] = bi[tid];
        else if (tid < 8)       sbias[tid] = be[tid - 4];
        if (tid == 8)  s_bh = bh_[0];
        if (tid == 9)  s_bt = bt_[0];
        if (warp == 13) {
            int4 mv = ((const int4*)(mask + b * SZ))[lane];
            int v = mv.x + mv.y + mv.z + mv.w;
#pragma unroll
            for (int off = 16; off; off >>= 1) v += __shfl_xor_sync(0xFFFFFFFFu, v, off);
            if (lane == 0) s_len = v;
        }
    }
    __syncthreads();

    // ---- phase A: row dots for local rows 0..39 (16 warps x 3 rows) ----
    {
        const int lr0 = warp * 3;
        float4 v[3][6];
        bool ok[3];
#pragma unroll
        for (int r = 0; r < 3; r++) {
            int lr = lr0 + r;
            int gr = q * 32 + lr;
            ok[r] = (lr < 40) && (gr < SZ);
            if (ok[r]) {
                const float4* rp = (const float4*)(eb + (size_t)gr * HZ);
#pragma unroll
                for (int i = 0; i < 6; i++) v[r][i] = rp[lane + 32 * i];
            } else {
#pragma unroll
                for (int i = 0; i < 6; i++) v[r][i] = make_float4(0.f,0.f,0.f,0.f);
            }
        }
        float ah[3] = {0.f,0.f,0.f}, at[3] = {0.f,0.f,0.f};
        const float4* swh4 = (const float4*)swh;
        const float4* swt4 = (const float4*)swt;
#pragma unroll
        for (int i = 0; i < 6; i++) {
            float4 wv = swh4[lane + 32 * i];
            float4 tv = swt4[lane + 32 * i];
#pragma unroll
            for (int r = 0; r < 3; r++) {
                ah[r] += v[r][i].x * wv.x + v[r][i].y * wv.y
                       + v[r][i].z * wv.z + v[r][i].w * wv.w;
                at[r] += v[r][i].x * tv.x + v[r][i].y * tv.y
                       + v[r][i].z * tv.z + v[r][i].w * tv.w;
            }
        }
#pragma unroll
        for (int off = 16; off; off >>= 1) {
#pragma unroll
            for (int r = 0; r < 3; r++) {
                ah[r] += __shfl_xor_sync(0xFFFFFFFFu, ah[r], off);
                at[r] += __shfl_xor_sync(0xFFFFFFFFu, at[r], off);
            }
        }
        if (lane == 0) {
#pragma unroll
            for (int r = 0; r < 3; r++) {
                int lr = lr0 + r;
                if (lr < 40) {
                    sdot[0][lr] = at[r];
                    sdot[1][lr] = ah[r];
                }
            }
        }
    }
    __syncthreads();

    // ---- scores: warp = type*8 + width; lane = local start; warp top-4 ----
    {
        const int type = warp >> 3;         // 0=target, 1=holder
        const int m = warp & 7;             // width index
        const int sl = lane;
        const int sg = q * 32 + sl;
        const int gidx = m * SZ + sg;
        float s = 0.f;
        for (int r = 0; r <= m; r++) s += sdot[type][sl + r];
        const int len = s_len;
        bool valid = ((sg + m) < len) && (type == 0 || m < MH_);
        float bias = type ? s_bh : s_bt;
        float v = valid ? 1.f / (1.f + __expf(-(s * c_inv[m] + bias))) : -1.f;
        // hs @2560, ts @35328
        out[(type ? 2560 : 35328) + (size_t)b * 1024 + gidx] = v;

        unsigned u = __float_as_uint(v);
        u = (u & 0x80000000u) ? ~u : (u | 0x80000000u);
        unsigned long long k0 = ((unsigned long long)u << 32) | (unsigned)(0xFFFFFFFFu - gidx);
        unsigned long long k1 = 0ull, k2 = 0ull, k3 = 0ull;
        WARP_MERGE4(k0, k1, k2, k3);
        if (lane == 0) {
            cand[type][m * 4 + 0] = k0; cand[type][m * 4 + 1] = k1;
            cand[type][m * 4 + 2] = k2; cand[type][m * 4 + 3] = k3;
        }
    }
    __syncthreads();

    // ---- block merge 32 -> 4 (warp0 targets, warp1 holders) -> g_cand ----
    if (warp < 2) {
        unsigned long long k0 = cand[warp][lane], k1 = 0ull, k2 = 0ull, k3 = 0ull;
        WARP_MERGE4(k0, k1, k2, k3);
        if (lane == 0) {
            unsigned long long* dst = &g_cand[((b * 2 + warp) * 4 + q) * 4];
            dst[0] = k0; dst[1] = k1; dst[2] = k2; dst[3] = k3;
        }
    }

    // ---- election: 4th arriving block of this batch runs the tail ----
    __threadfence();
    __syncthreads();
    if (tid == 0) {
        unsigned old = atomicAdd(&g_tick[b], 1u);
        if (old == 3u) s_flag = 1;
    }
    __syncthreads();
    if (!s_flag) return;
    if (tid == 0) g_tick[b] = 0;
    __threadfence();

    // ================= Tail (one block per batch) =========================
    // merge 16 candidates per type
    if (warp < 2) {
        unsigned long long k0 = (lane < 16) ? g_cand[(b * 2 + warp) * 16 + lane] : 0ull;
        unsigned long long k1 = 0ull, k2 = 0ull, k3 = 0ull;
        WARP_MERGE4(k0, k1, k2, k3);
        if (lane == 0) {
            unsigned long long ks[4] = {k0, k1, k2, k3};
#pragma unroll
            for (int k = 0; k < KK; k++) {
                unsigned hi = (unsigned)(ks[k] >> 32);
                unsigned lo = (unsigned)ks[k];
                float v = (hi & 0x80000000u) ? __uint_as_float(hi ^ 0x80000000u)
                                             : __uint_as_float(~hi);
                topv[warp][k] = v;
                topi[warp][k] = (int)(0xFFFFFFFFu - lo);
            }
        }
    }
    __syncthreads();

    // rep dots: 2 warps per selected span (warps 0-7 target, 8-15 holder)
    {
        const int type = warp >> 3;
        const int span = (warp >> 1) & 3;
        const int half = warp & 1;
        const int idx = topi[type][span];
        const bool valid = topv[type][span] > 0.f;
        const int m = idx >> 7, s = idx & 127;
        const float invw = c_inv[m];
        const float4* wi4 = (const float4*)wi;
        const float4* we4 = (const float4*)we;

        float acc[8] = {0.f,0.f,0.f,0.f,0.f,0.f,0.f,0.f};
        if (valid) {
            float4 sum[3];
#pragma unroll
            for (int i = 0; i < 3; i++) sum[i] = make_float4(0.f,0.f,0.f,0.f);
            const int c0 = lane + 96 * half;
#pragma unroll
            for (int r = 0; r < 8; r++) {
                if (r <= m) {
                    const float4* rp = (const float4*)(eb + (size_t)(s + r) * HZ);
#pragma unroll
                    for (int i = 0; i < 3; i++) {
                        float4 a = rp[c0 + 32 * i];
                        sum[i].x += a.x; sum[i].y += a.y;
                        sum[i].z += a.z; sum[i].w += a.w;
                    }
                }
            }
#pragma unroll
            for (int i = 0; i < 3; i++) {
                int h4 = c0 + 32 * i;
                float sv[4] = {sum[i].x * invw, sum[i].y * invw,
                               sum[i].z * invw, sum[i].w * invw};
#pragma unroll
                for (int j = 0; j < 4; j++) {
                    int f = 4 * h4 + j;
                    if (type == 0) {
                        float4 wv = wi4[f];
                        acc[0] += sv[j] * wv.x; acc[1] += sv[j] * wv.y;
                        acc[2] += sv[j] * wv.z; acc[3] += sv[j] * wv.w;
                        float4 ev = we4[HZ + f];
                        acc[4] += sv[j] * ev.x; acc[5] += sv[j] * ev.y;
                        acc[6] += sv[j] * ev.z; acc[7] += sv[j] * ev.w;
                    } else {
                        float4 ev = we4[f];
                        acc[0] += sv[j] * ev.x; acc[1] += sv[j] * ev.y;
                        acc[2] += sv[j] * ev.z; acc[3] += sv[j] * ev.w;
                    }
                }
            }
        }
#pragma unroll
        for (int off = 16; off; off >>= 1)
#pragma unroll
            for (int j = 0; j < 8; j++)
                acc[j] += __shfl_xor_sync(0xFFFFFFFFu, acc[j], off);
        if (lane == 0) {
#pragma unroll
            for (int j = 0; j < 8; j++) partial[warp][j] = acc[j];
        }
    }
    __syncthreads();

    // logits
    if (tid < 64) {
        int k = tid >> 4, i = (tid >> 2) & 3, j = tid & 3;
        bool pv = (topv[1][k] > 0.f) && (topv[0][i] > 0.f);
        float val = sbias[4 + j];
        if (pv) val += partial[8 + 2*k][j] + partial[8 + 2*k + 1][j]
                     + partial[2*i][4 + j] + partial[2*i + 1][4 + j];
        out[512 + (size_t)b * 64 + tid] = val;
    } else if (tid < 80) {
        int t2 = tid - 64;
        int i = t2 >> 2, j = t2 & 3;
        float val = sbias[j];
        if (topv[0][i] > 0.f) val += partial[2*i][j] + partial[2*i + 1][j];
        out[(size_t)b * 16 + t2] = val;
    }
}

extern "C" void kernel_launch(void* const* d_in, const int* in_sizes, int n_in,
                              void* d_out, int out_size)
{
    const float* emb = (const float*)d_in[0];
    const int*   msk = (const int*)d_in[1];
    const float* wh  = (const float*)d_in[2];
    const float* bh  = (const float*)d_in[3];
    const float* wt  = (const float*)d_in[4];
    const float* bt  = (const float*)d_in[5];
    const float* wi  = (const float*)d_in[6];
    const float* bi  = (const float*)d_in[7];
    const float* we  = (const float*)d_in[8];
    const float* be  = (const float*)d_in[9];
    float* out = (float*)d_out;

    dim3 g(BZ, 4, 1);
    k_all<<<g, 512>>>(emb, msk, wh, bh, wt, bt, wi, bi, we, be, out);
}